// round 16
// baseline (speedup 1.0000x reference)
#include <cuda_runtime.h>
#include <math.h>

#define P_L1 20
#define P_R1 70
#define P_L2 120
#define P_R2 170
#define NFACT 10
#define TT 200
#define NTRIALS 256
#define NCONFIGS 128
#define TWN 50
#define WIN 53                        // softplus window [L-1, R+1]
#define PLANE (NTRIALS * NCONFIGS)    // 32768

#define N_FILL 4000                   // 1000 planes * 4 quarter-planes
#define N_WARP 5120                   // 20 k * 256 trials
#define N_TASK 9216                   // 576 groups * 16 (7 fill + 9 warp)
#define NBLOCKS 1776                  // 148 SMs * 12 resident blocks

// JAX softplus: max(x,0) + log1p(exp(-|x|))
__device__ __forceinline__ float softplus_f(float x) {
    return fmaxf(x, 0.0f) + log1pf(expf(-fabsf(x)));
}

__global__ void __launch_bounds__(128) fused_kernel(
    const float* __restrict__ beta,
    const float* __restrict__ toff,    // [256,128,20]
    const float* __restrict__ coff,    // [128,20]
    const float* __restrict__ timev,   // [200]
    float* __restrict__ out)
{
    const int tid  = threadIdx.x;
    const int lane = tid & 31;
    const int q    = tid >> 5;             // tw phase 0..3
    const int c0   = lane * 4;             // 4 consecutive configs per thread

    __shared__ float sf[WIN];

    // grid-stride over virtual tasks: same 7:9 fill/warp interleave as before,
    // but only one chip-wave of blocks -> no partial-wave tail.
    for (int task = blockIdx.x; task < N_TASK; task += NBLOCKS) {
        const int grp = task >> 4;
        const int sub = task & 15;

        if (sub < 7) {
            // ---------------- fill path: quarter-plane broadcast ------------
            int fid = grp * 7 + sub;       // 0..4031, valid 0..3999
            if (fid >= N_FILL) continue;
            int p    = fid >> 2;           // plane 0..999 = (l, static col j)
            int quad = fid & 3;
            int l = p / 100;
            int j = p - l * 100;
            int t = (j < P_L1) ? j : ((j < 70) ? j + 50 : j + 100);

            float v = softplus_f(beta[l * TT + t]);
            float4 v4 = make_float4(v, v, v, v);

            float4* op = (float4*)(out + (size_t)(l * TT + t) * PLANE)
                       + quad * (PLANE / 16);
            #pragma unroll 4
            for (int i = tid; i < PLANE / 16; i += 128)   // 2048 float4
                __stcs(&op[i], v4);
            continue;
        }

        // ------------------- warp path ----------------------------------
        const int wid = grp * 9 + (sub - 7);   // 0..5183, valid 0..5119
        if (wid >= N_WARP) continue;
        const int k   = wid >> 8;              // 0..19 (seg*10 + l)
        const int n   = wid & 255;             // trial
        const int seg = (k >= NFACT) ? 1 : 0;
        const int l   = k - seg * NFACT;
        const int Ls  = seg ? P_L2 : P_L1;
        const int Rs  = seg ? P_R2 : P_R1;

        __syncthreads();                       // protect sf from prior iteration
        if (tid < WIN)
            sf[tid] = softplus_f(beta[l * TT + (Ls - 1) + tid]);
        __syncthreads();

        // warp-parallel first-max argmax over sf[1..50] (each warp redundantly)
        float peak;
        {
            float bv = sf[1 + lane];
            int   bi = lane;                   // lanes cover elems 0..31
            if (lane < 18) {                   // elems 32..49
                float v2 = sf[33 + lane];
                if (v2 > bv) { bv = v2; bi = lane + 32; }
            }
            #pragma unroll
            for (int off = 16; off > 0; off >>= 1) {
                float ov = __shfl_xor_sync(0xffffffffu, bv, off);
                int   oi = __shfl_xor_sync(0xffffffffu, bi, off);
                if (ov > bv || (ov == bv && oi < bi)) { bv = ov; bi = oi; }
            }
            peak = timev[Ls + bi];
        }

        const float dt  = timev[1] - timev[0];
        const float rdt = 1.0f / dt;
        const float ll  = timev[Ls];
        const float rl  = timev[Rs];
        const float b1  = ll * rdt;            // left-branch intercept

        // per-config warp params (index-space affine pieces)
        float t0[4], a1[4], a2[4], b2[4];
        #pragma unroll
        for (int j = 0; j < 4; ++j) {
            int c = c0 + j;
            float s = peak + toff[(n * NCONFIGS + c) * (2 * NFACT) + k]
                           + coff[c * (2 * NFACT) + k];
            if (s <= ll) s = ll + dt;
            if (s >= rl) s = rl - dt;
            float lsp    = s - ll;
            float lslope = (peak - ll) / lsp;
            float rslope = (peak - rl) / (s - rl);
            t0[j] = lsp * rdt;                          // branch point (tw units)
            a1[j] = lslope;
            a2[j] = rslope;
            b2[j] = (peak - lsp * rslope) * rdt;        // right-branch intercept
        }

        // base float4 pointer at (l, Ls, n, c0)
        float4* op = (float4*)(out + ((size_t)(l * TT + Ls) * NTRIALS + n) * NCONFIGS + c0);

        #pragma unroll 1
        for (int tw = q; tw < TWN; tw += 4) {
            float twf = (float)tw;
            float4 v;
            float* vp = (float*)&v;
            #pragma unroll
            for (int j = 0; j < 4; ++j) {
                float wi = (twf < t0[j]) ? fmaf(twf, a1[j], b1)
                                         : fmaf(twf, a2[j], b2[j]);
                float fl = floorf(wi);
                float cw = wi - fl;
                int idx = (int)fl - (Ls - 1);
                idx = max(0, min(WIN - 2, idx));
                float f0 = sf[idx];
                float f1 = sf[idx + 1];
                vp[j] = fmaf(cw, f1 - f0, f0);
            }
            __stcs(&op[(size_t)tw * (PLANE / 4)], v);
        }
    }
}

// ---------------------------------------------------------------------------
extern "C" void kernel_launch(void* const* d_in, const int* in_sizes, int n_in,
                              void* d_out, int out_size)
{
    const float* beta = nullptr;
    const float* toff = nullptr;
    const float* coff = nullptr;
    const float* tim  = nullptr;
    for (int i = 0; i < n_in; ++i) {
        switch (in_sizes[i]) {
            case NFACT * TT:                      beta = (const float*)d_in[i]; break;
            case NTRIALS * NCONFIGS * 2 * NFACT:  toff = (const float*)d_in[i]; break;
            case NCONFIGS * 2 * NFACT:            coff = (const float*)d_in[i]; break;
            case TT:                              tim  = (const float*)d_in[i]; break;
            default: break;
        }
    }
    float* out = (float*)d_out;

    fused_kernel<<<NBLOCKS, 128>>>(beta, toff, coff, tim, out);
}

// round 17
// speedup vs baseline: 1.2789x; 1.2789x over previous
#include <cuda_runtime.h>
#include <math.h>

#define P_L1 20
#define P_R1 70
#define P_L2 120
#define P_R2 170
#define NFACT 10
#define TT 200
#define NTRIALS 256
#define NCONFIGS 128
#define TWN 50
#define WIN 53                        // softplus window [L-1, R+1]
#define PLANE (NTRIALS * NCONFIGS)    // 32768

#define N_FILL 4000                   // 1000 planes * 4 quarter-planes
#define N_WARP 5120                   // 20 k * 256 trials
#define GRP 16                        // 7 fill + 9 warp per group
#define NGRP 576

// JAX softplus: max(x,0) + log1p(exp(-|x|))
__device__ __forceinline__ float softplus_f(float x) {
    return fmaxf(x, 0.0f) + log1pf(expf(-fabsf(x)));
}

__global__ void __launch_bounds__(128) fused_kernel(
    const float* __restrict__ beta,
    const float* __restrict__ toff,    // [256,128,20]
    const float* __restrict__ coff,    // [128,20]
    const float* __restrict__ timev,   // [200]
    float* __restrict__ out)
{
    const int bid = blockIdx.x;
    const int grp = bid >> 4;
    const int sub = bid & 15;

    if (sub < 7) {
        // ---------------- fill path: quarter-plane broadcast ----------------
        int fid = grp * 7 + sub;           // 0..4031, valid 0..3999
        if (fid >= N_FILL) return;
        int p    = fid >> 2;               // plane 0..999 = (l, static col j)
        int quad = fid & 3;
        int l = p / 100;
        int j = p - l * 100;
        int t = (j < P_L1) ? j : ((j < 70) ? j + 50 : j + 100);

        float v = softplus_f(beta[l * TT + t]);
        float4 v4 = make_float4(v, v, v, v);

        float4* op = (float4*)(out + (size_t)(l * TT + t) * PLANE)
                   + quad * (PLANE / 16);
        #pragma unroll 4
        for (int i = threadIdx.x; i < PLANE / 16; i += 128)  // 2048 float4
            __stcs(&op[i], v4);
        return;
    }

    // ------------------- warp path --------------------------------------
    const int wid = grp * 9 + (sub - 7);   // 0..5183, valid 0..5119
    if (wid >= N_WARP) return;
    const int k   = wid >> 8;              // 0..19 (seg*10 + l)
    const int n   = wid & 255;             // trial
    const int seg = (k >= NFACT) ? 1 : 0;
    const int l   = k - seg * NFACT;
    const int Ls  = seg ? P_L2 : P_L1;
    const int Rs  = seg ? P_R2 : P_R1;

    const int tid  = threadIdx.x;
    const int lane = tid & 31;
    const int q    = tid >> 5;             // tw phase 0..3
    const int c0   = lane * 4;             // 4 consecutive configs per thread

    __shared__ float sf[WIN];

    if (tid < WIN)
        sf[tid] = softplus_f(beta[l * TT + (Ls - 1) + tid]);
    __syncthreads();

    // warp-parallel first-max argmax over sf[1..50] (each warp redundantly)
    float peak;
    {
        float bv = sf[1 + lane];
        int   bi = lane;                   // lanes cover elems 0..31
        if (lane < 18) {                   // elems 32..49
            float v2 = sf[33 + lane];
            if (v2 > bv) { bv = v2; bi = lane + 32; }
        }
        #pragma unroll
        for (int off = 16; off > 0; off >>= 1) {
            float ov = __shfl_xor_sync(0xffffffffu, bv, off);
            int   oi = __shfl_xor_sync(0xffffffffu, bi, off);
            if (ov > bv || (ov == bv && oi < bi)) { bv = ov; bi = oi; }
        }
        peak = timev[Ls + bi];
    }

    const float dt  = timev[1] - timev[0];
    const float rdt = 1.0f / dt;
    const float ll  = timev[Ls];
    const float rl  = timev[Rs];
    const float b1  = ll * rdt;            // left-branch intercept (index space)

    // per-config warp params (index-space affine pieces)
    float t0[4], a1[4], a2[4], b2[4];
    #pragma unroll
    for (int j = 0; j < 4; ++j) {
        int c = c0 + j;
        float s = peak + toff[(n * NCONFIGS + c) * (2 * NFACT) + k]
                       + coff[c * (2 * NFACT) + k];
        if (s <= ll) s = ll + dt;
        if (s >= rl) s = rl - dt;
        float lsp    = s - ll;
        float lslope = (peak - ll) / lsp;
        float rslope = (peak - rl) / (s - rl);
        t0[j] = lsp * rdt;                          // branch point in tw units
        a1[j] = lslope;
        a2[j] = rslope;
        b2[j] = (peak - lsp * rslope) * rdt;        // right-branch intercept
    }

    // base float4 pointer at (l, Ls, n, c0)
    float4* op = (float4*)(out + ((size_t)(l * TT + Ls) * NTRIALS + n) * NCONFIGS + c0);

    #pragma unroll 1
    for (int tw = q; tw < TWN; tw += 4) {
        float twf = (float)tw;
        float4 v;
        float* vp = (float*)&v;
        #pragma unroll
        for (int j = 0; j < 4; ++j) {
            float wi = (twf < t0[j]) ? fmaf(twf, a1[j], b1)
                                     : fmaf(twf, a2[j], b2[j]);
            float fl = floorf(wi);
            float cw = wi - fl;
            int idx = (int)fl - (Ls - 1);
            idx = max(0, min(WIN - 2, idx));
            float f0 = sf[idx];
            float f1 = sf[idx + 1];
            vp[j] = fmaf(cw, f1 - f0, f0);
        }
        __stcs(&op[(size_t)tw * (PLANE / 4)], v);
    }
}

// ---------------------------------------------------------------------------
extern "C" void kernel_launch(void* const* d_in, const int* in_sizes, int n_in,
                              void* d_out, int out_size)
{
    const float* beta = nullptr;
    const float* toff = nullptr;
    const float* coff = nullptr;
    const float* tim  = nullptr;
    for (int i = 0; i < n_in; ++i) {
        switch (in_sizes[i]) {
            case NFACT * TT:                      beta = (const float*)d_in[i]; break;
            case NTRIALS * NCONFIGS * 2 * NFACT:  toff = (const float*)d_in[i]; break;
            case NCONFIGS * 2 * NFACT:            coff = (const float*)d_in[i]; break;
            case TT:                              tim  = (const float*)d_in[i]; break;
            default: break;
        }
    }
    float* out = (float*)d_out;

    fused_kernel<<<NGRP * GRP, 128>>>(beta, toff, coff, tim, out);
}